// round 3
// baseline (speedup 1.0000x reference)
#include <cuda_runtime.h>
#include <cuda_bf16.h>

// SoftmaxPooling: y[g] = sum_{i in g} exp(Xa[i]) * X[i] / sum_{i in g} exp(Xa[i])
// graph_idx sorted ascending -> segments are contiguous node ranges.
// Pass 1: boundary kernel writes seg_start[g] (first node index with gidx >= g).
// Pass 2: persistent grid (1332 blocks ~= 9/SM x 148 SMs), each block
//         grid-strides over graphs; per graph: 4 warps stream rows with
//         float4 loads, smem cross-warp reduce, no atomics.

#define D 128
#define MAX_GRAPHS (4 * 1024 * 1024)
#define POOL_BLOCKS 1332

__device__ int g_seg_start[MAX_GRAPHS + 1];

__global__ void boundaries_kernel(const int* __restrict__ gidx,
                                  int n_nodes, int n_graphs)
{
    int i = blockIdx.x * blockDim.x + threadIdx.x;   // i in [0, n_nodes]
    if (i > n_nodes) return;
    int cur = (i < n_nodes) ? gidx[i] : n_graphs;
    int prv = (i > 0) ? gidx[i - 1] : -1;
    if (cur > n_graphs) cur = n_graphs;
    for (int g = prv + 1; g <= cur; ++g)
        g_seg_start[g] = i;
}

__global__ __launch_bounds__(D) void softmax_pool_kernel(
    const float* __restrict__ X,
    const float* __restrict__ Xatt,
    float*       __restrict__ out,
    int n_graphs)
{
    const int t = threadIdx.x;
    const int w = t >> 5;          // warp 0..3
    const int l = t & 31;          // lane -> columns [4l, 4l+4)

    __shared__ float4 s_a[4][32];
    __shared__ float4 s_w[4][32];

    for (int g = blockIdx.x; g < n_graphs; g += gridDim.x) {

        const int start = g_seg_start[g];
        const int end   = g_seg_start[g + 1];

        float4 aa0 = {0.f,0.f,0.f,0.f}, ww0 = {0.f,0.f,0.f,0.f};
        float4 aa1 = {0.f,0.f,0.f,0.f}, ww1 = {0.f,0.f,0.f,0.f};

        int i = start + w;
        for (; i + 4 < end; i += 8) {
            const float4* pxa0 = (const float4*)(Xatt + (size_t)i * D) + l;
            const float4* px0  = (const float4*)(X    + (size_t)i * D) + l;
            const float4* pxa1 = (const float4*)(Xatt + (size_t)(i + 4) * D) + l;
            const float4* px1  = (const float4*)(X    + (size_t)(i + 4) * D) + l;
            float4 xa0 = __ldcs(pxa0);
            float4 x0  = __ldcs(px0);
            float4 xa1 = __ldcs(pxa1);
            float4 x1  = __ldcs(px1);

            float4 a0, a1;
            a0.x = __expf(xa0.x); a0.y = __expf(xa0.y); a0.z = __expf(xa0.z); a0.w = __expf(xa0.w);
            a1.x = __expf(xa1.x); a1.y = __expf(xa1.y); a1.z = __expf(xa1.z); a1.w = __expf(xa1.w);

            aa0.x += a0.x; aa0.y += a0.y; aa0.z += a0.z; aa0.w += a0.w;
            ww0.x = fmaf(a0.x, x0.x, ww0.x); ww0.y = fmaf(a0.y, x0.y, ww0.y);
            ww0.z = fmaf(a0.z, x0.z, ww0.z); ww0.w = fmaf(a0.w, x0.w, ww0.w);

            aa1.x += a1.x; aa1.y += a1.y; aa1.z += a1.z; aa1.w += a1.w;
            ww1.x = fmaf(a1.x, x1.x, ww1.x); ww1.y = fmaf(a1.y, x1.y, ww1.y);
            ww1.z = fmaf(a1.z, x1.z, ww1.z); ww1.w = fmaf(a1.w, x1.w, ww1.w);
        }
        for (; i < end; i += 4) {
            const float4* pxa = (const float4*)(Xatt + (size_t)i * D) + l;
            const float4* px  = (const float4*)(X    + (size_t)i * D) + l;
            float4 xa = __ldcs(pxa);
            float4 x  = __ldcs(px);
            float4 a;
            a.x = __expf(xa.x); a.y = __expf(xa.y); a.z = __expf(xa.z); a.w = __expf(xa.w);
            aa0.x += a.x; aa0.y += a.y; aa0.z += a.z; aa0.w += a.w;
            ww0.x = fmaf(a.x, x.x, ww0.x); ww0.y = fmaf(a.y, x.y, ww0.y);
            ww0.z = fmaf(a.z, x.z, ww0.z); ww0.w = fmaf(a.w, x.w, ww0.w);
        }

        aa0.x += aa1.x; aa0.y += aa1.y; aa0.z += aa1.z; aa0.w += aa1.w;
        ww0.x += ww1.x; ww0.y += ww1.y; ww0.z += ww1.z; ww0.w += ww1.w;

        s_a[w][l] = aa0;
        s_w[w][l] = ww0;
        __syncthreads();

        if (t < 32) {
            float4 A = s_a[0][t], W = s_w[0][t];
            #pragma unroll
            for (int k = 1; k < 4; ++k) {
                float4 a = s_a[k][t], wv = s_w[k][t];
                A.x += a.x; A.y += a.y; A.z += a.z; A.w += a.w;
                W.x += wv.x; W.y += wv.y; W.z += wv.z; W.w += wv.w;
            }
            float4 r;
            r.x = W.x / A.x; r.y = W.y / A.y; r.z = W.z / A.z; r.w = W.w / A.w;
            ((float4*)(out + (size_t)g * D))[t] = r;
        }
        __syncthreads();   // protect smem reuse for next graph
    }
}

extern "C" void kernel_launch(void* const* d_in, const int* in_sizes, int n_in,
                              void* d_out, int out_size)
{
    const float* X    = (const float*)d_in[0];
    const float* Xatt = (const float*)d_in[1];
    const int*   gidx = (const int*)d_in[2];

    const int n_nodes  = in_sizes[2];
    const int n_graphs = in_sizes[3];
    (void)n_in; (void)out_size;

    int bthreads = 256;
    int bblocks  = (n_nodes + 1 + bthreads - 1) / bthreads;
    boundaries_kernel<<<bblocks, bthreads>>>(gidx, n_nodes, n_graphs);

    int pblocks = POOL_BLOCKS < n_graphs ? POOL_BLOCKS : n_graphs;
    softmax_pool_kernel<<<pblocks, D>>>(X, Xatt, (float*)d_out, n_graphs);
}

// round 4
// speedup vs baseline: 1.1119x; 1.1119x over previous
#include <cuda_runtime.h>
#include <cuda_bf16.h>

// SoftmaxPooling: y[g] = sum_{i in g} exp(Xa[i]) * X[i] / sum_{i in g} exp(Xa[i])
// graph_idx sorted ascending -> segments are contiguous node ranges.
// Pass 1: boundary kernel writes seg_start[g] (first node index with gidx >= g).
// Pass 2: one WARP per graph. Lane l owns columns [4l, 4l+4) (float4).
//         No syncthreads, no smem, no atomics. One-shot blocks (4 graphs/block)
//         so the work distributor overlaps block tails.

#define D 128
#define MAX_GRAPHS (4 * 1024 * 1024)

__device__ int g_seg_start[MAX_GRAPHS + 1];

__global__ void boundaries_kernel(const int* __restrict__ gidx,
                                  int n_nodes, int n_graphs)
{
    int i = blockIdx.x * blockDim.x + threadIdx.x;   // i in [0, n_nodes]
    if (i > n_nodes) return;
    int cur = (i < n_nodes) ? gidx[i] : n_graphs;
    int prv = (i > 0) ? gidx[i - 1] : -1;
    if (cur > n_graphs) cur = n_graphs;
    for (int g = prv + 1; g <= cur; ++g)
        g_seg_start[g] = i;
}

__global__ __launch_bounds__(128) void softmax_pool_kernel(
    const float* __restrict__ X,
    const float* __restrict__ Xatt,
    float*       __restrict__ out,
    int n_graphs)
{
    const int warp = (blockIdx.x << 2) | (threadIdx.x >> 5);  // global warp = graph id
    const int l    = threadIdx.x & 31;                        // lane -> cols [4l, 4l+4)
    if (warp >= n_graphs) return;

    const int start = g_seg_start[warp];
    const int end   = g_seg_start[warp + 1];

    float4 aa = {0.f,0.f,0.f,0.f};
    float4 ww = {0.f,0.f,0.f,0.f};

    const float4* pXa = (const float4*)(Xatt) + l;   // +32 per row
    const float4* pX  = (const float4*)(X)    + l;

    int i = start;
    for (; i + 1 < end; i += 2) {
        const size_t r0 = (size_t)i * 32;
        const size_t r1 = (size_t)(i + 1) * 32;
        float4 xa0 = __ldcs(pXa + r0);
        float4 x0  = __ldcs(pX  + r0);
        float4 xa1 = __ldcs(pXa + r1);
        float4 x1  = __ldcs(pX  + r1);

        float4 a0, a1;
        a0.x = __expf(xa0.x); a0.y = __expf(xa0.y); a0.z = __expf(xa0.z); a0.w = __expf(xa0.w);
        a1.x = __expf(xa1.x); a1.y = __expf(xa1.y); a1.z = __expf(xa1.z); a1.w = __expf(xa1.w);

        aa.x += a0.x; aa.y += a0.y; aa.z += a0.z; aa.w += a0.w;
        ww.x = fmaf(a0.x, x0.x, ww.x); ww.y = fmaf(a0.y, x0.y, ww.y);
        ww.z = fmaf(a0.z, x0.z, ww.z); ww.w = fmaf(a0.w, x0.w, ww.w);

        aa.x += a1.x; aa.y += a1.y; aa.z += a1.z; aa.w += a1.w;
        ww.x = fmaf(a1.x, x1.x, ww.x); ww.y = fmaf(a1.y, x1.y, ww.y);
        ww.z = fmaf(a1.z, x1.z, ww.z); ww.w = fmaf(a1.w, x1.w, ww.w);
    }
    if (i < end) {
        const size_t r = (size_t)i * 32;
        float4 xa = __ldcs(pXa + r);
        float4 x  = __ldcs(pX  + r);
        float4 a;
        a.x = __expf(xa.x); a.y = __expf(xa.y); a.z = __expf(xa.z); a.w = __expf(xa.w);
        aa.x += a.x; aa.y += a.y; aa.z += a.z; aa.w += a.w;
        ww.x = fmaf(a.x, x.x, ww.x); ww.y = fmaf(a.y, x.y, ww.y);
        ww.z = fmaf(a.z, x.z, ww.z); ww.w = fmaf(a.w, x.w, ww.w);
    }

    float4 r;
    r.x = ww.x / aa.x; r.y = ww.y / aa.y; r.z = ww.z / aa.z; r.w = ww.w / aa.w;
    ((float4*)(out + (size_t)warp * D))[l] = r;
}

extern "C" void kernel_launch(void* const* d_in, const int* in_sizes, int n_in,
                              void* d_out, int out_size)
{
    const float* X    = (const float*)d_in[0];
    const float* Xatt = (const float*)d_in[1];
    const int*   gidx = (const int*)d_in[2];

    const int n_nodes  = in_sizes[2];
    const int n_graphs = in_sizes[3];
    (void)n_in; (void)out_size;

    int bthreads = 256;
    int bblocks  = (n_nodes + 1 + bthreads - 1) / bthreads;
    boundaries_kernel<<<bblocks, bthreads>>>(gidx, n_nodes, n_graphs);

    int pblocks = (n_graphs + 3) / 4;   // 4 warps (graphs) per block
    softmax_pool_kernel<<<pblocks, 128>>>(X, Xatt, (float*)d_out, n_graphs);
}

// round 5
// speedup vs baseline: 1.1728x; 1.0548x over previous
#include <cuda_runtime.h>
#include <cuda_bf16.h>

// SoftmaxPooling: y[g] = sum_{i in g} exp(Xa[i]) * X[i] / sum_{i in g} exp(Xa[i])
// graph_idx sorted ascending -> segments are contiguous node ranges.
// Pass 1: boundary kernel writes seg_start[g].
// Pass 2: one CTA per graph (R2 schedule: 4 warps stride rows by 4, unroll 2,
//         float4 lanes, __ldcs), lean register body + launch_bounds(128,12)
//         to raise occupancy -> more outstanding LDG.128.

#define D 128
#define MAX_GRAPHS (4 * 1024 * 1024)

__device__ int g_seg_start[MAX_GRAPHS + 1];

__global__ void boundaries_kernel(const int* __restrict__ gidx,
                                  int n_nodes, int n_graphs)
{
    int i = blockIdx.x * blockDim.x + threadIdx.x;   // i in [0, n_nodes]
    if (i > n_nodes) return;
    int cur = (i < n_nodes) ? gidx[i] : n_graphs;
    int prv = (i > 0) ? gidx[i - 1] : -1;
    if (cur > n_graphs) cur = n_graphs;
    for (int g = prv + 1; g <= cur; ++g)
        g_seg_start[g] = i;
}

__global__ __launch_bounds__(128, 12) void softmax_pool_kernel(
    const float* __restrict__ X,
    const float* __restrict__ Xatt,
    float*       __restrict__ out)
{
    const int g = blockIdx.x;
    const int t = threadIdx.x;
    const int w = t >> 5;          // warp 0..3
    const int l = t & 31;          // lane -> columns [4l, 4l+4)

    const int start = g_seg_start[g];
    const int end   = g_seg_start[g + 1];

    float4 aa = {0.f,0.f,0.f,0.f};
    float4 ww = {0.f,0.f,0.f,0.f};

    // running pointers for row (start + w); row step 4 -> +128 float4s
    const float4* pXa = (const float4*)(Xatt) + (size_t)(start + w) * 32 + l;
    const float4* pX  = (const float4*)(X)    + (size_t)(start + w) * 32 + l;

    int i = start + w;
    for (; i + 4 < end; i += 8) {
        float4 xa0 = __ldcs(pXa);
        float4 x0  = __ldcs(pX);
        float4 xa1 = __ldcs(pXa + 128);
        float4 x1  = __ldcs(pX  + 128);
        pXa += 256; pX += 256;

        xa0.x = __expf(xa0.x); xa0.y = __expf(xa0.y); xa0.z = __expf(xa0.z); xa0.w = __expf(xa0.w);
        xa1.x = __expf(xa1.x); xa1.y = __expf(xa1.y); xa1.z = __expf(xa1.z); xa1.w = __expf(xa1.w);

        aa.x += xa0.x; aa.y += xa0.y; aa.z += xa0.z; aa.w += xa0.w;
        ww.x = fmaf(xa0.x, x0.x, ww.x); ww.y = fmaf(xa0.y, x0.y, ww.y);
        ww.z = fmaf(xa0.z, x0.z, ww.z); ww.w = fmaf(xa0.w, x0.w, ww.w);

        aa.x += xa1.x; aa.y += xa1.y; aa.z += xa1.z; aa.w += xa1.w;
        ww.x = fmaf(xa1.x, x1.x, ww.x); ww.y = fmaf(xa1.y, x1.y, ww.y);
        ww.z = fmaf(xa1.z, x1.z, ww.z); ww.w = fmaf(xa1.w, x1.w, ww.w);
    }
    for (; i < end; i += 4) {
        float4 xa = __ldcs(pXa);
        float4 x  = __ldcs(pX);
        pXa += 128; pX += 128;
        xa.x = __expf(xa.x); xa.y = __expf(xa.y); xa.z = __expf(xa.z); xa.w = __expf(xa.w);
        aa.x += xa.x; aa.y += xa.y; aa.z += xa.z; aa.w += xa.w;
        ww.x = fmaf(xa.x, x.x, ww.x); ww.y = fmaf(xa.y, x.y, ww.y);
        ww.z = fmaf(xa.z, x.z, ww.z); ww.w = fmaf(xa.w, x.w, ww.w);
    }

    __shared__ float4 s_a[4][32];
    __shared__ float4 s_w[4][32];
    s_a[w][l] = aa;
    s_w[w][l] = ww;
    __syncthreads();

    if (t < 32) {
        float4 A = s_a[0][t], W = s_w[0][t];
        #pragma unroll
        for (int k = 1; k < 4; ++k) {
            float4 a = s_a[k][t], wv = s_w[k][t];
            A.x += a.x; A.y += a.y; A.z += a.z; A.w += a.w;
            W.x += wv.x; W.y += wv.y; W.z += wv.z; W.w += wv.w;
        }
        float4 r;
        r.x = W.x / A.x; r.y = W.y / A.y; r.z = W.z / A.z; r.w = W.w / A.w;
        ((float4*)(out + (size_t)g * D))[t] = r;
    }
}

extern "C" void kernel_launch(void* const* d_in, const int* in_sizes, int n_in,
                              void* d_out, int out_size)
{
    const float* X    = (const float*)d_in[0];
    const float* Xatt = (const float*)d_in[1];
    const int*   gidx = (const int*)d_in[2];

    const int n_nodes  = in_sizes[2];
    const int n_graphs = in_sizes[3];
    (void)n_in; (void)out_size;

    int bthreads = 256;
    int bblocks  = (n_nodes + 1 + bthreads - 1) / bthreads;
    boundaries_kernel<<<bblocks, bthreads>>>(gidx, n_nodes, n_graphs);

    softmax_pool_kernel<<<n_graphs, D>>>(X, Xatt, (float*)d_out);
}

// round 6
// speedup vs baseline: 1.1761x; 1.0028x over previous
#include <cuda_runtime.h>
#include <cuda_bf16.h>

// SoftmaxPooling: y[g] = sum_{i in g} exp(Xa[i]) * X[i] / sum_{i in g} exp(Xa[i])
// graph_idx sorted ascending -> segments are contiguous node ranges.
// Pass 1: vectorized boundary kernel (int4): seg_start[g] = first i with gidx[i] >= g.
// Pass 2: one CTA per graph: 4 warps stride rows by 4, float4 lanes, unroll 2,
//         __ldcs streaming loads, smem cross-warp reduce. (R5 kernel, proven best.)

#define D 128
#define MAX_GRAPHS (4 * 1024 * 1024)

__device__ int g_seg_start[MAX_GRAPHS + 1];

__global__ void boundaries_kernel(const int* __restrict__ gidx,
                                  int n_nodes, int n_graphs)
{
    // thread t handles node indices [4t, 4t+4); one extra virtual element i == n_nodes
    const int t  = blockIdx.x * blockDim.x + threadIdx.x;
    const int i0 = t << 2;
    if (i0 > n_nodes) return;

    int v[4];
    if (i0 + 3 < n_nodes) {
        int4 q = *(const int4*)(gidx + i0);
        v[0] = q.x; v[1] = q.y; v[2] = q.z; v[3] = q.w;
    } else {
        #pragma unroll
        for (int k = 0; k < 4; ++k)
            v[k] = (i0 + k < n_nodes) ? gidx[i0 + k] : n_graphs;
    }

    int prv = (i0 > 0) ? gidx[i0 - 1] : -1;

    #pragma unroll
    for (int k = 0; k < 4; ++k) {
        const int i = i0 + k;
        if (i > n_nodes) break;
        int cur = v[k];
        if (cur > n_graphs) cur = n_graphs;
        for (int g = prv + 1; g <= cur; ++g)
            g_seg_start[g] = i;
        prv = cur;
    }
}

__global__ __launch_bounds__(128, 12) void softmax_pool_kernel(
    const float* __restrict__ X,
    const float* __restrict__ Xatt,
    float*       __restrict__ out)
{
    const int g = blockIdx.x;
    const int t = threadIdx.x;
    const int w = t >> 5;          // warp 0..3
    const int l = t & 31;          // lane -> columns [4l, 4l+4)

    const int start = g_seg_start[g];
    const int end   = g_seg_start[g + 1];

    float4 aa = {0.f,0.f,0.f,0.f};
    float4 ww = {0.f,0.f,0.f,0.f};

    const float4* pXa = (const float4*)(Xatt) + (size_t)(start + w) * 32 + l;
    const float4* pX  = (const float4*)(X)    + (size_t)(start + w) * 32 + l;

    int i = start + w;
    for (; i + 4 < end; i += 8) {
        float4 xa0 = __ldcs(pXa);
        float4 x0  = __ldcs(pX);
        float4 xa1 = __ldcs(pXa + 128);
        float4 x1  = __ldcs(pX  + 128);
        pXa += 256; pX += 256;

        xa0.x = __expf(xa0.x); xa0.y = __expf(xa0.y); xa0.z = __expf(xa0.z); xa0.w = __expf(xa0.w);
        xa1.x = __expf(xa1.x); xa1.y = __expf(xa1.y); xa1.z = __expf(xa1.z); xa1.w = __expf(xa1.w);

        aa.x += xa0.x; aa.y += xa0.y; aa.z += xa0.z; aa.w += xa0.w;
        ww.x = fmaf(xa0.x, x0.x, ww.x); ww.y = fmaf(xa0.y, x0.y, ww.y);
        ww.z = fmaf(xa0.z, x0.z, ww.z); ww.w = fmaf(xa0.w, x0.w, ww.w);

        aa.x += xa1.x; aa.y += xa1.y; aa.z += xa1.z; aa.w += xa1.w;
        ww.x = fmaf(xa1.x, x1.x, ww.x); ww.y = fmaf(xa1.y, x1.y, ww.y);
        ww.z = fmaf(xa1.z, x1.z, ww.z); ww.w = fmaf(xa1.w, x1.w, ww.w);
    }
    for (; i < end; i += 4) {
        float4 xa = __ldcs(pXa);
        float4 x  = __ldcs(pX);
        pXa += 128; pX += 128;
        xa.x = __expf(xa.x); xa.y = __expf(xa.y); xa.z = __expf(xa.z); xa.w = __expf(xa.w);
        aa.x += xa.x; aa.y += xa.y; aa.z += xa.z; aa.w += xa.w;
        ww.x = fmaf(xa.x, x.x, ww.x); ww.y = fmaf(xa.y, x.y, ww.y);
        ww.z = fmaf(xa.z, x.z, ww.z); ww.w = fmaf(xa.w, x.w, ww.w);
    }

    __shared__ float4 s_a[4][32];
    __shared__ float4 s_w[4][32];
    s_a[w][l] = aa;
    s_w[w][l] = ww;
    __syncthreads();

    if (t < 32) {
        float4 A = s_a[0][t], W = s_w[0][t];
        #pragma unroll
        for (int k = 1; k < 4; ++k) {
            float4 a = s_a[k][t], wv = s_w[k][t];
            A.x += a.x; A.y += a.y; A.z += a.z; A.w += a.w;
            W.x += wv.x; W.y += wv.y; W.z += wv.z; W.w += wv.w;
        }
        float4 r;
        r.x = W.x / A.x; r.y = W.y / A.y; r.z = W.z / A.z; r.w = W.w / A.w;
        ((float4*)(out + (size_t)g * D))[t] = r;
    }
}

extern "C" void kernel_launch(void* const* d_in, const int* in_sizes, int n_in,
                              void* d_out, int out_size)
{
    const float* X    = (const float*)d_in[0];
    const float* Xatt = (const float*)d_in[1];
    const int*   gidx = (const int*)d_in[2];

    const int n_nodes  = in_sizes[2];
    const int n_graphs = in_sizes[3];
    (void)n_in; (void)out_size;

    // one thread per 4 nodes, plus the virtual i == n_nodes element
    int bthreads = 256;
    int work     = (n_nodes >> 2) + 1;
    int bblocks  = (work + bthreads - 1) / bthreads;
    boundaries_kernel<<<bblocks, bthreads>>>(gidx, n_nodes, n_graphs);

    softmax_pool_kernel<<<n_graphs, D>>>(X, Xatt, (float*)d_out);
}